// round 1
// baseline (speedup 1.0000x reference)
#include <cuda_runtime.h>

// Problem constants
#define NBATCH 4096
#define NTOK   64
#define NDIM   256
#define NHEADS 8
#define HD     32
#define NROWS  (NBATCH * NTOK)   // 262144

// Scratch (allocation-free rule: __device__ globals)
__device__ float g_q[NBATCH * NHEADS * NTOK * HD];   // 256 MB, q pre-scaled
__device__ float g_k[NBATCH * NHEADS * NTOK * HD];
__device__ float g_v[NBATCH * NHEADS * NTOK * HD];
__device__ float g_o[NBATCH * NTOK * NDIM];          // attention output, [B*N, 256]

// ---------------------------------------------------------------------------
// Kernel 1: QKV projection. y[262144, 768] = x[262144,256] @ [wq | wkv] + bias
// BM=64 (one window per row-block), BN=64, BK=16, 256 threads, 4x4 microtile.
// Epilogue scatters into q (scaled), k, v in [B,H,N,dh] layout.
// ---------------------------------------------------------------------------
__global__ __launch_bounds__(256) void qkv_gemm(
    const float* __restrict__ x, const float* __restrict__ wq,
    const float* __restrict__ bq, const float* __restrict__ wkv,
    const float* __restrict__ bkv)
{
    __shared__ float As[16][64];
    __shared__ float Bs[16][64];
    const int t   = threadIdx.x;
    const int win = blockIdx.y;      // window == 64-row block
    const int bn  = blockIdx.x;      // 64-col block, 0..11

    const float* W; int ld, cb;
    if (bn < 4) { W = wq;  ld = 256; cb = bn * 64; }
    else        { W = wkv; ld = 512; cb = bn * 64 - 256; }

    const int arow = t >> 2;
    const int acol = (t & 3) << 2;
    const float* xrow = x + ((size_t)win * 64 + arow) * 256 + acol;

    const int brow = t >> 4;
    const int bcol = (t & 15) << 2;
    const float* wp = W + (size_t)brow * ld + cb + bcol;

    const int tx = t & 15, ty = t >> 4;

    float acc[4][4];
#pragma unroll
    for (int i = 0; i < 4; i++)
#pragma unroll
        for (int j = 0; j < 4; j++) acc[i][j] = 0.f;

    for (int k0 = 0; k0 < 256; k0 += 16) {
        float4 av = *(const float4*)(xrow + k0);
        As[acol + 0][arow] = av.x;
        As[acol + 1][arow] = av.y;
        As[acol + 2][arow] = av.z;
        As[acol + 3][arow] = av.w;
        *(float4*)&Bs[brow][bcol] = *(const float4*)(wp + (size_t)k0 * ld);
        __syncthreads();
#pragma unroll
        for (int kk = 0; kk < 16; kk++) {
            const float4 a4 = *(const float4*)&As[kk][ty << 2];
            const float4 b4 = *(const float4*)&Bs[kk][tx << 2];
            const float ar[4] = {a4.x, a4.y, a4.z, a4.w};
            const float br[4] = {b4.x, b4.y, b4.z, b4.w};
#pragma unroll
            for (int i = 0; i < 4; i++)
#pragma unroll
                for (int j = 0; j < 4; j++)
                    acc[i][j] += ar[i] * br[j];
        }
        __syncthreads();
    }

    const float scale = 0.17677669529663687f;  // 32^-0.5
#pragma unroll
    for (int i = 0; i < 4; i++) {
        const int n = (ty << 2) + i;
#pragma unroll
        for (int j = 0; j < 4; j++) {
            const int c = bn * 64 + (tx << 2) + j;   // 0..767 (uniform region per block)
            float vv = acc[i][j];
            if (c < 256) {
                vv = (vv + bq[c]) * scale;
                const int h = c >> 5, d = c & 31;
                g_q[(((size_t)win * NHEADS + h) * NTOK + n) * HD + d] = vv;
            } else {
                vv += bkv[c - 256];
                const int c2 = c - 256;
                if (c2 < 256) {
                    const int h = c2 >> 5, d = c2 & 31;
                    g_k[(((size_t)win * NHEADS + h) * NTOK + n) * HD + d] = vv;
                } else {
                    const int c3 = c2 - 256;
                    const int h = c3 >> 5, d = c3 & 31;
                    g_v[(((size_t)win * NHEADS + h) * NTOK + n) * HD + d] = vv;
                }
            }
        }
    }
}

// ---------------------------------------------------------------------------
// Kernel 2: fused attention per (batch, head). 64 threads; thread t owns row t.
//   S = (q*scale) @ k^T + bias[rel_idx][h]
//   A = ww0 * softmax(S) + ww1 * relu(S)^2
//   O = A @ v  ->  g_o[B*N, 256] at column h*32
// ---------------------------------------------------------------------------
__global__ __launch_bounds__(64) void attn_kernel(
    const float* __restrict__ bias_table, const int* __restrict__ rel_idx,
    const float* __restrict__ w)
{
    __shared__ float Qs[NTOK][HD];
    __shared__ float Ks[NTOK][HD];
    __shared__ float Vs[NTOK][HD];
    const int bh = blockIdx.x;     // 0 .. B*H-1
    const int h  = bh & 7;
    const int t  = threadIdx.x;

    const float* qb = g_q + (size_t)bh * NTOK * HD;
    const float* kb = g_k + (size_t)bh * NTOK * HD;
    const float* vb = g_v + (size_t)bh * NTOK * HD;
    float* Qf = &Qs[0][0];
    float* Kf = &Ks[0][0];
    float* Vf = &Vs[0][0];
#pragma unroll
    for (int i = 0; i < 8; i++) {
        const int idx = (i * 64 + t) * 4;
        *(float4*)(Qf + idx) = *(const float4*)(qb + idx);
        *(float4*)(Kf + idx) = *(const float4*)(kb + idx);
        *(float4*)(Vf + idx) = *(const float4*)(vb + idx);
    }
    __syncthreads();

    // mixing weights ww = softmax(w)
    const float w0 = w[0], w1 = w[1];
    const float wm = fmaxf(w0, w1);
    const float ee0 = __expf(w0 - wm), ee1 = __expf(w1 - wm);
    const float winv = 1.f / (ee0 + ee1);
    const float ww0 = ee0 * winv, ww1 = ee1 * winv;

    const int n = t;
    float qr[HD];
#pragma unroll
    for (int i = 0; i < 8; i++) {
        const float4 v4 = *(const float4*)&Qs[n][i * 4];
        qr[i * 4 + 0] = v4.x; qr[i * 4 + 1] = v4.y;
        qr[i * 4 + 2] = v4.z; qr[i * 4 + 3] = v4.w;
    }

    float s[NTOK];
#pragma unroll
    for (int m = 0; m < NTOK; m++) {
        float a = 0.f;
#pragma unroll
        for (int i = 0; i < 8; i++) {
            const float4 kv = *(const float4*)&Ks[m][i * 4];
            a += qr[i * 4 + 0] * kv.x + qr[i * 4 + 1] * kv.y
               + qr[i * 4 + 2] * kv.z + qr[i * 4 + 3] * kv.w;
        }
        s[m] = a;
    }

    const int* ri = rel_idx + n * NTOK;
#pragma unroll
    for (int m = 0; m < NTOK; m++)
        s[m] += bias_table[ri[m] * NHEADS + h];

    float mx = -1e30f;
#pragma unroll
    for (int m = 0; m < NTOK; m++) mx = fmaxf(mx, s[m]);

    float ex[NTOK];
    float sum = 0.f;
#pragma unroll
    for (int m = 0; m < NTOK; m++) {
        const float e = __expf(s[m] - mx);
        ex[m] = e;
        sum += e;
        const float r = fmaxf(s[m], 0.f);
        s[m] = r * r;                    // relu^2 term replaces raw score
    }
    const float c0 = ww0 / sum;
#pragma unroll
    for (int m = 0; m < NTOK; m++)
        s[m] = ex[m] * c0 + s[m] * ww1;  // combined attention weight

    float o[HD];
#pragma unroll
    for (int d = 0; d < HD; d++) o[d] = 0.f;
#pragma unroll
    for (int m = 0; m < NTOK; m++) {
        const float am = s[m];
#pragma unroll
        for (int i = 0; i < 8; i++) {
            const float4 vv = *(const float4*)&Vs[m][i * 4];
            o[i * 4 + 0] += am * vv.x; o[i * 4 + 1] += am * vv.y;
            o[i * 4 + 2] += am * vv.z; o[i * 4 + 3] += am * vv.w;
        }
    }

    float* op = g_o + ((size_t)(bh >> 3) * NTOK + n) * NDIM + h * HD;
#pragma unroll
    for (int i = 0; i < 8; i++) {
        float4 vv;
        vv.x = o[i * 4 + 0]; vv.y = o[i * 4 + 1];
        vv.z = o[i * 4 + 2]; vv.w = o[i * 4 + 3];
        *(float4*)(op + i * 4) = vv;
    }
}

// ---------------------------------------------------------------------------
// Kernel 3: output projection. out[262144,256] = g_o @ proj_w + proj_b
// ---------------------------------------------------------------------------
__global__ __launch_bounds__(256) void proj_gemm(
    const float* __restrict__ pw, const float* __restrict__ pb,
    float* __restrict__ out)
{
    __shared__ float As[16][64];
    __shared__ float Bs[16][64];
    const int t  = threadIdx.x;
    const int bm = blockIdx.y;      // 64-row block over 262144 rows
    const int bn = blockIdx.x;      // 0..3
    const int cb = bn * 64;

    const int arow = t >> 2;
    const int acol = (t & 3) << 2;
    const float* xrow = g_o + ((size_t)bm * 64 + arow) * 256 + acol;

    const int brow = t >> 4;
    const int bcol = (t & 15) << 2;
    const float* wp = pw + (size_t)brow * 256 + cb + bcol;

    const int tx = t & 15, ty = t >> 4;

    float acc[4][4];
#pragma unroll
    for (int i = 0; i < 4; i++)
#pragma unroll
        for (int j = 0; j < 4; j++) acc[i][j] = 0.f;

    for (int k0 = 0; k0 < 256; k0 += 16) {
        float4 av = *(const float4*)(xrow + k0);
        As[acol + 0][arow] = av.x;
        As[acol + 1][arow] = av.y;
        As[acol + 2][arow] = av.z;
        As[acol + 3][arow] = av.w;
        *(float4*)&Bs[brow][bcol] = *(const float4*)(wp + (size_t)k0 * 256);
        __syncthreads();
#pragma unroll
        for (int kk = 0; kk < 16; kk++) {
            const float4 a4 = *(const float4*)&As[kk][ty << 2];
            const float4 b4 = *(const float4*)&Bs[kk][tx << 2];
            const float ar[4] = {a4.x, a4.y, a4.z, a4.w};
            const float br[4] = {b4.x, b4.y, b4.z, b4.w};
#pragma unroll
            for (int i = 0; i < 4; i++)
#pragma unroll
                for (int j = 0; j < 4; j++)
                    acc[i][j] += ar[i] * br[j];
        }
        __syncthreads();
    }

#pragma unroll
    for (int i = 0; i < 4; i++) {
        const int r = (ty << 2) + i;
#pragma unroll
        for (int j = 0; j < 4; j++) {
            const int c = cb + (tx << 2) + j;
            out[((size_t)bm * 64 + r) * 256 + c] = acc[i][j] + pb[c];
        }
    }
}

// ---------------------------------------------------------------------------
extern "C" void kernel_launch(void* const* d_in, const int* in_sizes, int n_in,
                              void* d_out, int out_size)
{
    const float* x   = (const float*)d_in[0];
    const float* wq  = (const float*)d_in[1];
    const float* bq  = (const float*)d_in[2];
    const float* wkv = (const float*)d_in[3];
    const float* bkv = (const float*)d_in[4];
    const float* bt  = (const float*)d_in[5];
    const float* w   = (const float*)d_in[6];
    const float* pw  = (const float*)d_in[7];
    const float* pb  = (const float*)d_in[8];
    const int*   ri  = (const int*)d_in[9];
    float* out = (float*)d_out;

    qkv_gemm<<<dim3(12, NBATCH), 256>>>(x, wq, bq, wkv, bkv);
    attn_kernel<<<NBATCH * NHEADS, 64>>>(bt, ri, w);
    proj_gemm<<<dim3(4, NBATCH), 256>>>(pw, pb, out);
}

// round 3
// speedup vs baseline: 2.6354x; 2.6354x over previous
#include <cuda_runtime.h>
#include <cstdint>

#define NBATCH 4096
#define NTOK   64
#define NDIM   256
#define NHEADS 8
#define HD     32
#define NROWS  (NBATCH * NTOK)   // 262144

// ---------------- device scratch (allocation-free rule) ---------------------
__device__ float g_q[NBATCH * NHEADS * NTOK * HD];
__device__ float g_k[NBATCH * NHEADS * NTOK * HD];
__device__ float g_v[NBATCH * NHEADS * NTOK * HD];
__device__ float g_o[NBATCH * NTOK * NDIM];
__device__ float g_wtq[768 * 256];        // [col][k], tf32-rounded
__device__ float g_wtp[256 * 256];        // [col][k], tf32-rounded
__device__ float g_bias[NHEADS * NTOK * NTOK];  // [h][n][m]

__device__ __forceinline__ uint32_t f2tf32(float x) {
    uint32_t r;
    asm("cvt.rna.tf32.f32 %0, %1;" : "=r"(r) : "f"(x));
    return r;
}

__device__ __forceinline__ void mma8(float* c, const uint32_t* a, const uint32_t* b) {
    asm volatile(
        "mma.sync.aligned.m16n8k8.row.col.f32.tf32.tf32.f32 "
        "{%0,%1,%2,%3}, {%4,%5,%6,%7}, {%8,%9}, {%0,%1,%2,%3};"
        : "+f"(c[0]), "+f"(c[1]), "+f"(c[2]), "+f"(c[3])
        : "r"(a[0]), "r"(a[1]), "r"(a[2]), "r"(a[3]), "r"(b[0]), "r"(b[1]));
}

// ---------------------------------------------------------------------------
// Prep: weight transpose (+tf32 rounding) and per-head bias matrix.
// ---------------------------------------------------------------------------
__global__ void prep_w(const float* __restrict__ wq, const float* __restrict__ wkv,
                       const float* __restrict__ pw)
{
    int idx = blockIdx.x * 256 + threadIdx.x;
    if (idx < 768 * 256) {
        int c = idx >> 8, k = idx & 255;
        float v = (c < 256) ? wq[k * 256 + c] : wkv[k * 512 + (c - 256)];
        g_wtq[idx] = __uint_as_float(f2tf32(v));
    }
    int idx2 = idx - 768 * 256;
    if (idx2 >= 0 && idx2 < 256 * 256) {
        int c = idx2 >> 8, k = idx2 & 255;
        g_wtp[idx2] = __uint_as_float(f2tf32(pw[k * 256 + c]));
    }
}

__global__ void prep_bias(const float* __restrict__ bias_table,
                          const int* __restrict__ rel_idx)
{
    int idx = blockIdx.x * 256 + threadIdx.x;   // [0, 8*4096)
    int h = idx >> 12, rm = idx & 4095;
    g_bias[idx] = bias_table[rel_idx[rm] * NHEADS + h];
}

// ---------------------------------------------------------------------------
// tf32 mma.sync GEMM: C[128x128] = A[128x256] @ Wt^T(+bias)
// 128 threads = 4 warps (2x2), warp tile 64x64 (mtiles=4, ntiles=8).
// mode 0: qkv scatter into g_q (scaled) / g_k / g_v. mode 1: proj -> out.
// ---------------------------------------------------------------------------
__global__ __launch_bounds__(128) void mm_mma(
    const float* __restrict__ A, const float* __restrict__ Wt,
    const float* __restrict__ bq, const float* __restrict__ bkv,
    const float* __restrict__ pb, float* __restrict__ outp, int mode)
{
    __shared__ float As[128][36];
    __shared__ float Bs[128][36];
    const int t = threadIdx.x;
    const int lane = t & 31, wid = t >> 5;
    const int wm = wid & 1, wn = wid >> 1;
    const int gid = lane >> 2, tid4 = lane & 3;
    const size_t row0 = (size_t)blockIdx.y * 128;
    const int col0 = blockIdx.x * 128;

    float c[4][8][4];
#pragma unroll
    for (int mt = 0; mt < 4; mt++)
#pragma unroll
        for (int nt = 0; nt < 8; nt++)
#pragma unroll
            for (int i = 0; i < 4; i++) c[mt][nt][i] = 0.f;

    for (int k0 = 0; k0 < 256; k0 += 32) {
#pragma unroll
        for (int j = 0; j < 8; j++) {
            int idx = j * 128 + t;            // 1024 float4s of A tile
            int r = idx >> 3, q = idx & 7;
            float4 v = *(const float4*)(A + (row0 + r) * 256 + k0 + q * 4);
            uint4 u;
            u.x = f2tf32(v.x); u.y = f2tf32(v.y); u.z = f2tf32(v.z); u.w = f2tf32(v.w);
            *(uint4*)&As[r][q * 4] = u;
        }
#pragma unroll
        for (int j = 0; j < 8; j++) {
            int idx = j * 128 + t;
            int n = idx >> 3, q = idx & 7;
            *(float4*)&Bs[n][q * 4] =
                *(const float4*)(Wt + (size_t)(col0 + n) * 256 + k0 + q * 4);
        }
        __syncthreads();

#pragma unroll
        for (int kk = 0; kk < 4; kk++) {
            const int kb = kk * 8;
            uint32_t a[4][4], b[8][2];
#pragma unroll
            for (int mt = 0; mt < 4; mt++) {
                const int r = wm * 64 + mt * 16 + gid;
                a[mt][0] = __float_as_uint(As[r][kb + tid4]);
                a[mt][1] = __float_as_uint(As[r + 8][kb + tid4]);
                a[mt][2] = __float_as_uint(As[r][kb + tid4 + 4]);
                a[mt][3] = __float_as_uint(As[r + 8][kb + tid4 + 4]);
            }
#pragma unroll
            for (int nt = 0; nt < 8; nt++) {
                const int n = wn * 64 + nt * 8 + gid;
                b[nt][0] = __float_as_uint(Bs[n][kb + tid4]);
                b[nt][1] = __float_as_uint(Bs[n][kb + tid4 + 4]);
            }
#pragma unroll
            for (int mt = 0; mt < 4; mt++)
#pragma unroll
                for (int nt = 0; nt < 8; nt++)
                    mma8(c[mt][nt], a[mt], b[nt]);
        }
        __syncthreads();
    }

    // ---- epilogue ----
#pragma unroll
    for (int mt = 0; mt < 4; mt++) {
        const int rbase = wm * 64 + mt * 16 + gid;
#pragma unroll
        for (int h8 = 0; h8 < 2; h8++) {
            const size_t grow = row0 + rbase + h8 * 8;
#pragma unroll
            for (int nt = 0; nt < 8; nt++) {
                const int cib = wn * 64 + nt * 8 + tid4 * 2;
                const float v0 = c[mt][nt][h8 * 2 + 0];
                const float v1 = c[mt][nt][h8 * 2 + 1];
                if (mode) {
                    const float2 pbv = *(const float2*)(pb + col0 + cib);
                    float2 o2; o2.x = v0 + pbv.x; o2.y = v1 + pbv.y;
                    *(float2*)(outp + grow * 256 + col0 + cib) = o2;
                } else {
                    const int region = col0 >> 8;          // 0=q 1=k 2=v
                    const int c2 = col0 - (region << 8) + cib;
                    const float* bias = (region == 0) ? bq
                                       : (region == 1) ? bkv : (bkv + 256);
                    const float2 bv = *(const float2*)(bias + c2);
                    const float scl = (region == 0) ? 0.17677669529663687f : 1.0f;
                    float* dst = (region == 0) ? g_q : (region == 1) ? g_k : g_v;
                    const int win = (int)(grow >> 6), nn = (int)(grow & 63);
                    const int hh = c2 >> 5, d = c2 & 31;
                    float2 o2;
                    o2.x = (v0 + bv.x) * scl;
                    o2.y = (v1 + bv.y) * scl;
                    *(float2*)(dst + (((size_t)win * NHEADS + hh) * NTOK + nn) * HD + d) = o2;
                }
            }
        }
    }
}

// ---------------------------------------------------------------------------
// Attention per (batch, head). 128 threads: thread (r = t&63, half = t>>6)
// owns row r, key/value columns [half*32, half*32+32). Scores in registers.
// ---------------------------------------------------------------------------
__global__ __launch_bounds__(128) void attn_kernel(const float* __restrict__ w)
{
    __shared__ float Ks[NTOK][HD];
    __shared__ float Vs[NTOK][HD];
    __shared__ float Os[NTOK][HD + 1];
    __shared__ float Psum[NTOK][2];
    const int bh = blockIdx.x, h = bh & 7;
    const int t = threadIdx.x, r = t & 63, half = t >> 6;

    const float* kb = g_k + (size_t)bh * (NTOK * HD);
    const float* vb = g_v + (size_t)bh * (NTOK * HD);
#pragma unroll
    for (int j = 0; j < 4; j++) {
        const int i = (j * 128 + t) * 4;
        *(float4*)(&Ks[0][0] + i) = *(const float4*)(kb + i);
        *(float4*)(&Vs[0][0] + i) = *(const float4*)(vb + i);
    }

    float qr[HD];
    const float* qrow = g_q + (size_t)bh * (NTOK * HD) + r * HD;
#pragma unroll
    for (int j = 0; j < 8; j++) {
        const float4 v = *(const float4*)(qrow + j * 4);
        qr[j * 4 + 0] = v.x; qr[j * 4 + 1] = v.y;
        qr[j * 4 + 2] = v.z; qr[j * 4 + 3] = v.w;
    }
    float bb[32];
    const float* brow = g_bias + ((size_t)h * NTOK + r) * NTOK + half * 32;
#pragma unroll
    for (int j = 0; j < 8; j++) {
        const float4 v = *(const float4*)(brow + j * 4);
        bb[j * 4 + 0] = v.x; bb[j * 4 + 1] = v.y;
        bb[j * 4 + 2] = v.z; bb[j * 4 + 3] = v.w;
    }
    __syncthreads();

    const int m0 = half * 32;
    float s[32];
    float psum = 0.f;
#pragma unroll
    for (int j = 0; j < 32; j++) {
        const float* kr = Ks[m0 + j];
        float a = bb[j];
#pragma unroll
        for (int i = 0; i < 8; i++) {
            const float4 kv = *(const float4*)(kr + i * 4);
            a = fmaf(qr[i * 4 + 0], kv.x, a);
            a = fmaf(qr[i * 4 + 1], kv.y, a);
            a = fmaf(qr[i * 4 + 2], kv.z, a);
            a = fmaf(qr[i * 4 + 3], kv.w, a);
        }
        s[j] = a;
        psum += __expf(a);
    }
    Psum[r][half] = psum;
    __syncthreads();

    const float w0 = w[0], w1 = w[1];
    const float wm = fmaxf(w0, w1);
    const float e0 = __expf(w0 - wm), e1 = __expf(w1 - wm);
    const float winv = 1.f / (e0 + e1);
    const float total = Psum[r][0] + Psum[r][1];
    const float c0 = (e0 * winv) / total;
    const float c1 = e1 * winv;

    float o[HD];
#pragma unroll
    for (int d = 0; d < HD; d++) o[d] = 0.f;
#pragma unroll
    for (int j = 0; j < 32; j++) {
        const float sv = s[j];
        const float rr = fmaxf(sv, 0.f);
        const float a = __expf(sv) * c0 + rr * rr * c1;
        const float* vr = Vs[m0 + j];
#pragma unroll
        for (int i = 0; i < 8; i++) {
            const float4 vv = *(const float4*)(vr + i * 4);
            o[i * 4 + 0] = fmaf(a, vv.x, o[i * 4 + 0]);
            o[i * 4 + 1] = fmaf(a, vv.y, o[i * 4 + 1]);
            o[i * 4 + 2] = fmaf(a, vv.z, o[i * 4 + 2]);
            o[i * 4 + 3] = fmaf(a, vv.w, o[i * 4 + 3]);
        }
    }

    if (half == 1) {
#pragma unroll
        for (int d = 0; d < HD; d++) Os[r][d] = o[d];
    }
    __syncthreads();
    if (half == 0) {
        float* op = g_o + ((size_t)(bh >> 3) * NTOK + r) * NDIM + h * HD;
#pragma unroll
        for (int i = 0; i < 8; i++) {
            float4 vv;
            vv.x = o[i * 4 + 0] + Os[r][i * 4 + 0];
            vv.y = o[i * 4 + 1] + Os[r][i * 4 + 1];
            vv.z = o[i * 4 + 2] + Os[r][i * 4 + 2];
            vv.w = o[i * 4 + 3] + Os[r][i * 4 + 3];
            *(float4*)(op + i * 4) = vv;
        }
    }
}

// ---------------------------------------------------------------------------
extern "C" void kernel_launch(void* const* d_in, const int* in_sizes, int n_in,
                              void* d_out, int out_size)
{
    const float* x   = (const float*)d_in[0];
    const float* wq  = (const float*)d_in[1];
    const float* bq  = (const float*)d_in[2];
    const float* wkv = (const float*)d_in[3];
    const float* bkv = (const float*)d_in[4];
    const float* bt  = (const float*)d_in[5];
    const float* w   = (const float*)d_in[6];
    const float* pw  = (const float*)d_in[7];
    const float* pb  = (const float*)d_in[8];
    const int*   ri  = (const int*)d_in[9];
    float* out = (float*)d_out;

    float *wtq, *wtp, *go;
    cudaGetSymbolAddress((void**)&wtq, g_wtq);
    cudaGetSymbolAddress((void**)&wtp, g_wtp);
    cudaGetSymbolAddress((void**)&go,  g_o);

    prep_w<<<1024, 256>>>(wq, wkv, pw);
    prep_bias<<<128, 256>>>(bt, ri);
    mm_mma<<<dim3(6, NROWS / 128), 128>>>(x, wtq, bq, bkv, nullptr, nullptr, 0);
    attn_kernel<<<NBATCH * NHEADS, 128>>>(w);
    mm_mma<<<dim3(2, NROWS / 128), 128>>>(go, wtp, nullptr, nullptr, pb, out, 1);
}

// round 4
// speedup vs baseline: 2.8346x; 1.0756x over previous
#include <cuda_runtime.h>
#include <cstdint>

#define NBATCH 4096
#define NTOK   64
#define NDIM   256
#define NHEADS 8
#define HD     32
#define NROWS  (NBATCH * NTOK)   // 262144

// ---------------- device scratch ---------------------------------------------
__device__ float g_q[NBATCH * NHEADS * NTOK * HD];
__device__ float g_k[NBATCH * NHEADS * NTOK * HD];
__device__ float g_v[NBATCH * NHEADS * NTOK * HD];
__device__ float g_o[NBATCH * NTOK * NDIM];
__device__ float g_wtq[768 * 256];        // [col][k], tf32-rounded
__device__ float g_wtp[256 * 256];        // [col][k], tf32-rounded
__device__ float g_bias[NHEADS * NTOK * NTOK];  // [h][n][m]

__device__ __forceinline__ uint32_t f2tf32(float x) {
    uint32_t r;
    asm("cvt.rna.tf32.f32 %0, %1;" : "=r"(r) : "f"(x));
    return r;
}

__device__ __forceinline__ void mma8(float* c, const uint32_t* a, const uint32_t* b) {
    asm volatile(
        "mma.sync.aligned.m16n8k8.row.col.f32.tf32.tf32.f32 "
        "{%0,%1,%2,%3}, {%4,%5,%6,%7}, {%8,%9}, {%0,%1,%2,%3};"
        : "+f"(c[0]), "+f"(c[1]), "+f"(c[2]), "+f"(c[3])
        : "r"(a[0]), "r"(a[1]), "r"(a[2]), "r"(a[3]), "r"(b[0]), "r"(b[1]));
}

// ---------------------------------------------------------------------------
// Prep kernels
// ---------------------------------------------------------------------------
__global__ void prep_w(const float* __restrict__ wq, const float* __restrict__ wkv,
                       const float* __restrict__ pw)
{
    int idx = blockIdx.x * 256 + threadIdx.x;
    if (idx < 768 * 256) {
        int c = idx >> 8, k = idx & 255;
        float v = (c < 256) ? wq[k * 256 + c] : wkv[k * 512 + (c - 256)];
        g_wtq[idx] = __uint_as_float(f2tf32(v));
    }
    int idx2 = idx - 768 * 256;
    if (idx2 >= 0 && idx2 < 256 * 256) {
        int c = idx2 >> 8, k = idx2 & 255;
        g_wtp[idx2] = __uint_as_float(f2tf32(pw[k * 256 + c]));
    }
}

__global__ void prep_bias(const float* __restrict__ bias_table,
                          const int* __restrict__ rel_idx)
{
    int idx = blockIdx.x * 256 + threadIdx.x;   // [0, 8*4096)
    int h = idx >> 12, rm = idx & 4095;
    g_bias[idx] = bias_table[rel_idx[rm] * NHEADS + h];
}

// ---------------------------------------------------------------------------
// tf32 mma.sync GEMM with 2-stage smem double buffering. BK=16.
// 128 threads = 4 warps (2x2), warp tile 64x64.
// mode 0: qkv scatter into g_q (scaled) / g_k / g_v. mode 1: proj -> out.
// ---------------------------------------------------------------------------
__global__ __launch_bounds__(128, 2) void mm_mma(
    const float* __restrict__ A, const float* __restrict__ Wt,
    const float* __restrict__ bq, const float* __restrict__ bkv,
    const float* __restrict__ pb, float* __restrict__ outp, int mode)
{
    __shared__ float As[2][128][20];
    __shared__ float Bs[2][128][20];
    const int t = threadIdx.x;
    const int lane = t & 31, wid = t >> 5;
    const int wm = wid & 1, wn = wid >> 1;
    const int gid = lane >> 2, tid4 = lane & 3;
    const size_t row0 = (size_t)blockIdx.y * 128;
    const int col0 = blockIdx.x * 128;

    float c[4][8][4];
#pragma unroll
    for (int mt = 0; mt < 4; mt++)
#pragma unroll
        for (int nt = 0; nt < 8; nt++)
#pragma unroll
            for (int i = 0; i < 4; i++) c[mt][nt][i] = 0.f;

    // per-thread tile coords: 4 float4 each for A and B per 128x16 tile
    float4 pa[4], pb4[4];
#define LOAD_TILE(S)                                                            \
    do {                                                                        \
        const int k0 = (S) * 16;                                                \
        _Pragma("unroll")                                                       \
        for (int j = 0; j < 4; j++) {                                           \
            const int idx = j * 128 + t;                                        \
            const int r = idx >> 2, c4 = (idx & 3) * 4;                         \
            pa[j]  = *(const float4*)(A + (row0 + r) * 256 + k0 + c4);          \
            pb4[j] = *(const float4*)(Wt + (size_t)(col0 + r) * 256 + k0 + c4); \
        }                                                                       \
    } while (0)
#define STORE_TILE(BUF)                                                         \
    do {                                                                        \
        _Pragma("unroll")                                                       \
        for (int j = 0; j < 4; j++) {                                           \
            const int idx = j * 128 + t;                                        \
            const int r = idx >> 2, c4 = (idx & 3) * 4;                         \
            As[BUF][r][c4 + 0] = __uint_as_float(f2tf32(pa[j].x));              \
            As[BUF][r][c4 + 1] = __uint_as_float(f2tf32(pa[j].y));              \
            As[BUF][r][c4 + 2] = __uint_as_float(f2tf32(pa[j].z));              \
            As[BUF][r][c4 + 3] = __uint_as_float(f2tf32(pa[j].w));              \
            Bs[BUF][r][c4 + 0] = pb4[j].x;                                      \
            Bs[BUF][r][c4 + 1] = pb4[j].y;                                      \
            Bs[BUF][r][c4 + 2] = pb4[j].z;                                      \
            Bs[BUF][r][c4 + 3] = pb4[j].w;                                      \
        }                                                                       \
    } while (0)

    LOAD_TILE(0);
    STORE_TILE(0);
    __syncthreads();

    for (int s = 0; s < 16; s++) {
        const int cur = s & 1;
        if (s < 15) LOAD_TILE(s + 1);
#pragma unroll
        for (int kk = 0; kk < 2; kk++) {
            const int kb = kk * 8;
            uint32_t a[4][4], b[8][2];
#pragma unroll
            for (int mt = 0; mt < 4; mt++) {
                const int r = wm * 64 + mt * 16 + gid;
                a[mt][0] = __float_as_uint(As[cur][r][kb + tid4]);
                a[mt][1] = __float_as_uint(As[cur][r + 8][kb + tid4]);
                a[mt][2] = __float_as_uint(As[cur][r][kb + tid4 + 4]);
                a[mt][3] = __float_as_uint(As[cur][r + 8][kb + tid4 + 4]);
            }
#pragma unroll
            for (int nt = 0; nt < 8; nt++) {
                const int n = wn * 64 + nt * 8 + gid;
                b[nt][0] = __float_as_uint(Bs[cur][n][kb + tid4]);
                b[nt][1] = __float_as_uint(Bs[cur][n][kb + tid4 + 4]);
            }
#pragma unroll
            for (int mt = 0; mt < 4; mt++)
#pragma unroll
                for (int nt = 0; nt < 8; nt++)
                    mma8(c[mt][nt], a[mt], b[nt]);
        }
        if (s < 15) STORE_TILE(cur ^ 1);
        __syncthreads();
    }

    // ---- epilogue (same mapping as R3) ----
#pragma unroll
    for (int mt = 0; mt < 4; mt++) {
        const int rbase = wm * 64 + mt * 16 + gid;
#pragma unroll
        for (int h8 = 0; h8 < 2; h8++) {
            const size_t grow = row0 + rbase + h8 * 8;
#pragma unroll
            for (int nt = 0; nt < 8; nt++) {
                const int cib = wn * 64 + nt * 8 + tid4 * 2;
                const float v0 = c[mt][nt][h8 * 2 + 0];
                const float v1 = c[mt][nt][h8 * 2 + 1];
                if (mode) {
                    const float2 pbv = *(const float2*)(pb + col0 + cib);
                    float2 o2; o2.x = v0 + pbv.x; o2.y = v1 + pbv.y;
                    *(float2*)(outp + grow * 256 + col0 + cib) = o2;
                } else {
                    const int region = col0 >> 8;          // 0=q 1=k 2=v
                    const int c2 = col0 - (region << 8) + cib;
                    const float* bias = (region == 0) ? bq
                                       : (region == 1) ? bkv : (bkv + 256);
                    const float2 bv = *(const float2*)(bias + c2);
                    const float scl = (region == 0) ? 0.17677669529663687f : 1.0f;
                    float* dst = (region == 0) ? g_q : (region == 1) ? g_k : g_v;
                    const int win = (int)(grow >> 6), nn = (int)(grow & 63);
                    const int hh = c2 >> 5, d = c2 & 31;
                    float2 o2;
                    o2.x = (v0 + bv.x) * scl;
                    o2.y = (v1 + bv.y) * scl;
                    *(float2*)(dst + (((size_t)win * NHEADS + hh) * NTOK + nn) * HD + d) = o2;
                }
            }
        }
    }
#undef LOAD_TILE
#undef STORE_TILE
}

// ---------------------------------------------------------------------------
// Tensor-core attention. Block = one (b,h), 128 threads / 4 warps.
// Warp w owns rows [w*16, w*16+16).
//   S = Q@K^T via 3-term hi/lo tf32 (~fp32 accuracy) + bias
//   A = ww0*softmax(S) + ww1*relu(S)^2   (softmax on C-fragments, shfl reduce)
//   O = A@V via plain tf32 (A roundtrips through smem for fragment relayout)
// ---------------------------------------------------------------------------
__global__ __launch_bounds__(128, 2) void attn_mma(const float* __restrict__ w)
{
    __shared__ float Khi[64][33];
    __shared__ float Klo[64][33];
    __shared__ float Vs[64][33];
    __shared__ float Us[4][1088];   // per warp: qhi[16][33]@0, qlo@528; S[16][68] overlay

    const int bh = blockIdx.x, h = bh & 7;
    const int t = threadIdx.x, lane = t & 31, wid = t >> 5;
    const int gid = lane >> 2, t4 = lane & 3;

    const float* kb = g_k + (size_t)bh * 2048;
    const float* vb = g_v + (size_t)bh * 2048;
    const float* qb = g_q + (size_t)bh * 2048;

    // ---- cooperative fill: K hi/lo, V (tf32), Q hi/lo (warp-chunked) ----
#pragma unroll
    for (int j = 0; j < 4; j++) {
        const int idx = (j * 128 + t) * 4;
        const int r = idx >> 5, cc = idx & 31;
        float4 kv = *(const float4*)(kb + idx);
        float4 vv = *(const float4*)(vb + idx);
        float4 qv = *(const float4*)(qb + idx);
        float kh[4], vt[4], qh[4];
        const float kin[4] = {kv.x, kv.y, kv.z, kv.w};
        const float vin[4] = {vv.x, vv.y, vv.z, vv.w};
        const float qin[4] = {qv.x, qv.y, qv.z, qv.w};
        float* ub = Us[r >> 4];
        const int rl = r & 15;
#pragma unroll
        for (int e = 0; e < 4; e++) {
            kh[e] = __uint_as_float(f2tf32(kin[e]));
            Khi[r][cc + e] = kh[e];
            Klo[r][cc + e] = __uint_as_float(f2tf32(kin[e] - kh[e]));
            vt[e] = __uint_as_float(f2tf32(vin[e]));
            Vs[r][cc + e] = vt[e];
            qh[e] = __uint_as_float(f2tf32(qin[e]));
            ub[rl * 33 + cc + e] = qh[e];
            ub[528 + rl * 33 + cc + e] = __uint_as_float(f2tf32(qin[e] - qh[e]));
        }
    }
    __syncthreads();

    // ---- QK^T: 3-term hi/lo ----
    float c[8][4];
#pragma unroll
    for (int nt = 0; nt < 8; nt++)
#pragma unroll
        for (int i = 0; i < 4; i++) c[nt][i] = 0.f;

    const float* QH = Us[wid];
    const float* QL = Us[wid] + 528;
#pragma unroll
    for (int kc = 0; kc < 4; kc++) {
        const int kb8 = kc * 8;
        uint32_t ah[4], al[4];
        ah[0] = __float_as_uint(QH[gid * 33 + kb8 + t4]);
        ah[1] = __float_as_uint(QH[(gid + 8) * 33 + kb8 + t4]);
        ah[2] = __float_as_uint(QH[gid * 33 + kb8 + t4 + 4]);
        ah[3] = __float_as_uint(QH[(gid + 8) * 33 + kb8 + t4 + 4]);
        al[0] = __float_as_uint(QL[gid * 33 + kb8 + t4]);
        al[1] = __float_as_uint(QL[(gid + 8) * 33 + kb8 + t4]);
        al[2] = __float_as_uint(QL[gid * 33 + kb8 + t4 + 4]);
        al[3] = __float_as_uint(QL[(gid + 8) * 33 + kb8 + t4 + 4]);
#pragma unroll
        for (int nt = 0; nt < 8; nt++) {
            const int n = nt * 8 + gid;
            uint32_t bhh[2], bll[2];
            bhh[0] = __float_as_uint(Khi[n][kb8 + t4]);
            bhh[1] = __float_as_uint(Khi[n][kb8 + t4 + 4]);
            bll[0] = __float_as_uint(Klo[n][kb8 + t4]);
            bll[1] = __float_as_uint(Klo[n][kb8 + t4 + 4]);
            mma8(c[nt], ah, bhh);
            mma8(c[nt], ah, bll);
            mma8(c[nt], al, bhh);
        }
    }

    // ---- bias add ----
    const int r0 = wid * 16 + gid;        // block-local rows r0, r0+8
    const float* b0p = g_bias + ((size_t)h * 64 + r0) * 64;
    const float* b1p = b0p + 8 * 64;
#pragma unroll
    for (int nt = 0; nt < 8; nt++) {
        const int cc = nt * 8 + 2 * t4;
        const float2 x0 = *(const float2*)(b0p + cc);
        const float2 x1 = *(const float2*)(b1p + cc);
        c[nt][0] += x0.x; c[nt][1] += x0.y;
        c[nt][2] += x1.x; c[nt][3] += x1.y;
    }

    // ---- softmax sums (shfl over the 4 lanes sharing a row) ----
    float p0 = 0.f, p1 = 0.f;
#pragma unroll
    for (int nt = 0; nt < 8; nt++) {
        p0 += __expf(c[nt][0]) + __expf(c[nt][1]);
        p1 += __expf(c[nt][2]) + __expf(c[nt][3]);
    }
    p0 += __shfl_xor_sync(0xFFFFFFFF, p0, 1);
    p0 += __shfl_xor_sync(0xFFFFFFFF, p0, 2);
    p1 += __shfl_xor_sync(0xFFFFFFFF, p1, 1);
    p1 += __shfl_xor_sync(0xFFFFFFFF, p1, 2);

    const float w0 = w[0], w1 = w[1];
    const float wm = fmaxf(w0, w1);
    const float e0 = __expf(w0 - wm), e1 = __expf(w1 - wm);
    const float winv = 1.f / (e0 + e1);
    const float ww0 = e0 * winv, ww1 = e1 * winv;
    const float k00 = ww0 / p0, k01 = ww0 / p1;

    // ---- combined weights -> smem (tf32), overlaying this warp's Q region ----
    float* S = Us[wid];
#pragma unroll
    for (int nt = 0; nt < 8; nt++) {
        const int cc = nt * 8 + 2 * t4;
        float r00 = fmaxf(c[nt][0], 0.f), r01 = fmaxf(c[nt][1], 0.f);
        float r10 = fmaxf(c[nt][2], 0.f), r11 = fmaxf(c[nt][3], 0.f);
        S[gid * 68 + cc]           = __uint_as_float(f2tf32(__expf(c[nt][0]) * k00 + r00 * r00 * ww1));
        S[gid * 68 + cc + 1]       = __uint_as_float(f2tf32(__expf(c[nt][1]) * k00 + r01 * r01 * ww1));
        S[(gid + 8) * 68 + cc]     = __uint_as_float(f2tf32(__expf(c[nt][2]) * k01 + r10 * r10 * ww1));
        S[(gid + 8) * 68 + cc + 1] = __uint_as_float(f2tf32(__expf(c[nt][3]) * k01 + r11 * r11 * ww1));
    }
    __syncwarp();

    // ---- O = A @ V ----
    float o[4][4];
#pragma unroll
    for (int nt = 0; nt < 4; nt++)
#pragma unroll
        for (int i = 0; i < 4; i++) o[nt][i] = 0.f;

#pragma unroll
    for (int kc = 0; kc < 8; kc++) {
        const int kb8 = kc * 8;
        uint32_t a[4];
        a[0] = __float_as_uint(S[gid * 68 + kb8 + t4]);
        a[1] = __float_as_uint(S[(gid + 8) * 68 + kb8 + t4]);
        a[2] = __float_as_uint(S[gid * 68 + kb8 + t4 + 4]);
        a[3] = __float_as_uint(S[(gid + 8) * 68 + kb8 + t4 + 4]);
#pragma unroll
        for (int nt = 0; nt < 4; nt++) {
            uint32_t b[2];
            b[0] = __float_as_uint(Vs[kb8 + t4][nt * 8 + gid]);
            b[1] = __float_as_uint(Vs[kb8 + t4 + 4][nt * 8 + gid]);
            mma8(o[nt], a, b);
        }
    }

    // ---- write O: g_o[(win*64 + r)][h*32 + d] ----
    float* ob = g_o + ((size_t)(bh >> 3) * 64) * 256 + h * 32;
#pragma unroll
    for (int nt = 0; nt < 4; nt++) {
        const int d = nt * 8 + 2 * t4;
        float2 v0; v0.x = o[nt][0]; v0.y = o[nt][1];
        float2 v1; v1.x = o[nt][2]; v1.y = o[nt][3];
        *(float2*)(ob + (size_t)r0 * 256 + d) = v0;
        *(float2*)(ob + (size_t)(r0 + 8) * 256 + d) = v1;
    }
}

// ---------------------------------------------------------------------------
extern "C" void kernel_launch(void* const* d_in, const int* in_sizes, int n_in,
                              void* d_out, int out_size)
{
    const float* x   = (const float*)d_in[0];
    const float* wq  = (const float*)d_in[1];
    const float* bq  = (const float*)d_in[2];
    const float* wkv = (const float*)d_in[3];
    const float* bkv = (const float*)d_in[4];
    const float* bt  = (const float*)d_in[5];
    const float* w   = (const float*)d_in[6];
    const float* pw  = (const float*)d_in[7];
    const float* pb  = (const float*)d_in[8];
    const int*   ri  = (const int*)d_in[9];
    float* out = (float*)d_out;

    float *wtq, *wtp, *go;
    cudaGetSymbolAddress((void**)&wtq, g_wtq);
    cudaGetSymbolAddress((void**)&wtp, g_wtp);
    cudaGetSymbolAddress((void**)&go,  g_o);

    prep_w<<<1024, 256>>>(wq, wkv, pw);
    prep_bias<<<128, 256>>>(bt, ri);
    mm_mma<<<dim3(6, NROWS / 128), 128>>>(x, wtq, bq, bkv, nullptr, nullptr, 0);
    attn_mma<<<NBATCH * NHEADS, 128>>>(w);
    mm_mma<<<dim3(2, NROWS / 128), 128>>>(go, wtp, nullptr, nullptr, pb, out, 1);
}